// round 1
// baseline (speedup 1.0000x reference)
#include <cuda_runtime.h>
#include <cuda_bf16.h>
#include <cstddef>

#define D_IN  12544
#define D_HID 1024
#define MAXN  16000

// Scratch for intermediate activations (allocation-free rule: __device__ globals)
__device__ float g_h1[(size_t)MAXN * D_HID];
__device__ float g_h2[(size_t)MAXN * D_HID];

// ---------------------------------------------------------------------------
// Tiled SGEMM: C[M,N] = act(A[M,K] @ B[K,N] + bias), A row-major, B row-major.
// BM=128, BN=128, BK=16, 256 threads, 8x8 register tile per thread.
// M % 128 == 0, N % 128 == 0, K % 16 == 0 (holds: 16000, 1024, 12544/1024).
// ---------------------------------------------------------------------------
#define BM 128
#define BN 128
#define BK 16
#define TM 8
#define TN 8

__global__ __launch_bounds__(256, 2)
void gemm_bias_relu(const float* __restrict__ A,
                    const float* __restrict__ B,
                    const float* __restrict__ bias,
                    float* __restrict__ C,
                    int M, int N, int K, int do_relu)
{
    // Pad the M dimension of As to kill the 4-way store conflict
    __shared__ float As[BK][BM + 4];
    __shared__ float Bs[BK][BN];

    const int tid = threadIdx.x;
    const int tx  = tid & 15;   // N direction (16 threads)
    const int ty  = tid >> 4;   // M direction (16 threads)

    const int block_m = blockIdx.y * BM;
    const int block_n = blockIdx.x * BN;

    float acc[TM][TN];
#pragma unroll
    for (int i = 0; i < TM; i++)
#pragma unroll
        for (int j = 0; j < TN; j++) acc[i][j] = 0.0f;

    // A-tile loading: 128x16 floats = 512 float4 -> 2 per thread
    const int a_row  = tid >> 2;        // 0..63 (+64 second pass)
    const int a_col4 = (tid & 3) * 4;   // 0,4,8,12
    // B-tile loading: 16x128 floats = 512 float4 -> 2 per thread
    const int b_row  = tid >> 5;        // 0..7 (+8 second pass)
    const int b_col4 = (tid & 31) * 4;  // 0..124

    const float* Ab = A + (size_t)block_m * K;
    const float* Bb = B + block_n;

    for (int k0 = 0; k0 < K; k0 += BK) {
#pragma unroll
        for (int p = 0; p < 2; p++) {
            const int r = a_row + p * 64;
            const float4 v = *(const float4*)(Ab + (size_t)r * K + k0 + a_col4);
            As[a_col4 + 0][r] = v.x;
            As[a_col4 + 1][r] = v.y;
            As[a_col4 + 2][r] = v.z;
            As[a_col4 + 3][r] = v.w;
        }
#pragma unroll
        for (int p = 0; p < 2; p++) {
            const int r = b_row + p * 8;
            *(float4*)&Bs[r][b_col4] =
                *(const float4*)(Bb + (size_t)(k0 + r) * N + b_col4);
        }
        __syncthreads();

#pragma unroll
        for (int k = 0; k < BK; k++) {
            float a_reg[TM], b_reg[TN];
#pragma unroll
            for (int i = 0; i < TM; i++) a_reg[i] = As[k][ty * TM + i];
#pragma unroll
            for (int j = 0; j < TN; j++) b_reg[j] = Bs[k][tx * TN + j];
#pragma unroll
            for (int i = 0; i < TM; i++)
#pragma unroll
                for (int j = 0; j < TN; j++)
                    acc[i][j] = fmaf(a_reg[i], b_reg[j], acc[i][j]);
        }
        __syncthreads();
    }

    // Epilogue: bias + optional ReLU, vectorized stores
#pragma unroll
    for (int i = 0; i < TM; i++) {
        const int row = block_m + ty * TM + i;
#pragma unroll
        for (int j = 0; j < TN; j += 4) {
            const int col = block_n + tx * TN + j;
            float4 v;
            v.x = acc[i][j + 0] + bias[col + 0];
            v.y = acc[i][j + 1] + bias[col + 1];
            v.z = acc[i][j + 2] + bias[col + 2];
            v.w = acc[i][j + 3] + bias[col + 3];
            if (do_relu) {
                v.x = fmaxf(v.x, 0.0f);
                v.y = fmaxf(v.y, 0.0f);
                v.z = fmaxf(v.z, 0.0f);
                v.w = fmaxf(v.w, 0.0f);
            }
            *(float4*)(C + (size_t)row * N + col) = v;
        }
    }
}

// ---------------------------------------------------------------------------
// Heads: per-row GEMV against [1024 x 4] (Wc) and [1024 x 12] (Wr).
// One warp per row; each lane strides K, accumulates all 16 outputs, then
// butterfly-reduces. Output layout: [class_logits (M*4)] then [box_pred (M*12)].
// ---------------------------------------------------------------------------
__global__ __launch_bounds__(256)
void heads_kernel(const float* __restrict__ H,
                  const float* __restrict__ Wc, const float* __restrict__ bc,
                  const float* __restrict__ Wr, const float* __restrict__ br,
                  float* __restrict__ out, int M)
{
    const int warp = (blockIdx.x * blockDim.x + threadIdx.x) >> 5;
    const int lane = threadIdx.x & 31;
    if (warp >= M) return;

    const float* __restrict__ h = H + (size_t)warp * D_HID;
    float acc[16];
#pragma unroll
    for (int c = 0; c < 16; c++) acc[c] = 0.0f;

    for (int k = lane; k < D_HID; k += 32) {
        const float x = h[k];
        const float* wc = Wc + (size_t)k * 4;
#pragma unroll
        for (int c = 0; c < 4; c++) acc[c] = fmaf(x, wc[c], acc[c]);
        const float* wr = Wr + (size_t)k * 12;
#pragma unroll
        for (int c = 0; c < 12; c++) acc[4 + c] = fmaf(x, wr[c], acc[4 + c]);
    }

#pragma unroll
    for (int c = 0; c < 16; c++) {
#pragma unroll
        for (int off = 16; off > 0; off >>= 1)
            acc[c] += __shfl_xor_sync(0xffffffffu, acc[c], off);
    }

    if (lane < 4) {
        out[(size_t)warp * 4 + lane] = acc[lane] + bc[lane];
    } else if (lane < 16) {
        out[(size_t)M * 4 + (size_t)warp * 12 + (lane - 4)] = acc[lane] + br[lane - 4];
    }
}

// ---------------------------------------------------------------------------
extern "C" void kernel_launch(void* const* d_in, const int* in_sizes, int n_in,
                              void* d_out, int out_size)
{
    const float* X  = (const float*)d_in[0];
    const float* W1 = (const float*)d_in[1];
    const float* b1 = (const float*)d_in[2];
    const float* W2 = (const float*)d_in[3];
    const float* b2 = (const float*)d_in[4];
    const float* Wc = (const float*)d_in[5];
    const float* bc = (const float*)d_in[6];
    const float* Wr = (const float*)d_in[7];
    const float* br = (const float*)d_in[8];
    float* out = (float*)d_out;

    const int M = in_sizes[0] / D_IN;   // 16000

    float *h1 = nullptr, *h2 = nullptr;
    cudaGetSymbolAddress((void**)&h1, g_h1);
    cudaGetSymbolAddress((void**)&h2, g_h2);

    dim3 block(256);
    dim3 grid(D_HID / BN, M / BM);      // (8, 125)

    gemm_bias_relu<<<grid, block>>>(X,  W1, b1, h1, M, D_HID, D_IN,  1);
    gemm_bias_relu<<<grid, block>>>(h1, W2, b2, h2, M, D_HID, D_HID, 1);

    const int threads = 256;
    const int blocks  = (M * 32 + threads - 1) / threads;
    heads_kernel<<<blocks, threads>>>(h2, Wc, bc, Wr, br, out, M);
}

// round 3
// speedup vs baseline: 2.1554x; 2.1554x over previous
#include <cuda_runtime.h>
#include <cuda_bf16.h>
#include <cstdint>
#include <cstddef>

#define D_IN  12544
#define D_HID 1024
#define MAXN  16000

// ---------------- device scratch (allocation-free rule) ----------------
__device__ __align__(1024) __nv_bfloat16 g_Xhi[(size_t)MAXN * D_IN];
__device__ __align__(1024) __nv_bfloat16 g_Xlo[(size_t)MAXN * D_IN];
__device__ __align__(1024) __nv_bfloat16 g_W1hi[(size_t)D_HID * D_IN];  // [N][K]
__device__ __align__(1024) __nv_bfloat16 g_W1lo[(size_t)D_HID * D_IN];
__device__ __align__(1024) __nv_bfloat16 g_W2hi[(size_t)D_HID * D_HID];
__device__ __align__(1024) __nv_bfloat16 g_W2lo[(size_t)D_HID * D_HID];
__device__ __align__(1024) __nv_bfloat16 g_h1hi[(size_t)MAXN * D_HID];
__device__ __align__(1024) __nv_bfloat16 g_h1lo[(size_t)MAXN * D_HID];
__device__ float g_h2[(size_t)MAXN * D_HID];

// ---------------- asm helpers (baseline sm_90-level PTX only) ----------------
__device__ __forceinline__ uint32_t smem_u32(const void* p) {
    uint32_t a;
    asm("{ .reg .u64 t; cvta.to.shared.u64 t, %1; cvt.u32.u64 %0, t; }" : "=r"(a) : "l"(p));
    return a;
}
__device__ __forceinline__ void cp16(uint32_t dst, const void* src) {
    asm volatile("cp.async.cg.shared.global [%0], [%1], 16;" :: "r"(dst), "l"(src));
}
__device__ __forceinline__ void cp_commit() {
    asm volatile("cp.async.commit_group;" ::: "memory");
}
template <int N>
__device__ __forceinline__ void cp_wait() {
    asm volatile("cp.async.wait_group %0;" :: "n"(N) : "memory");
}
__device__ __forceinline__ void ldm_x4(uint32_t& r0, uint32_t& r1, uint32_t& r2, uint32_t& r3, uint32_t addr) {
    asm volatile("ldmatrix.sync.aligned.m8n8.x4.shared.b16 {%0,%1,%2,%3}, [%4];"
                 : "=r"(r0), "=r"(r1), "=r"(r2), "=r"(r3) : "r"(addr));
}
__device__ __forceinline__ void mma16816(float* c, const uint32_t* a, uint32_t b0, uint32_t b1) {
    asm volatile(
        "mma.sync.aligned.m16n8k16.row.col.f32.bf16.bf16.f32 "
        "{%0,%1,%2,%3}, {%4,%5,%6,%7}, {%8,%9}, {%0,%1,%2,%3};"
        : "+f"(c[0]), "+f"(c[1]), "+f"(c[2]), "+f"(c[3])
        : "r"(a[0]), "r"(a[1]), "r"(a[2]), "r"(a[3]), "r"(b0), "r"(b1));
}

// ---------------- GEMM: C[M,N] = act(A[M,K] @ B[N,K]^T + bias), bf16 hi/lo x3 ----------------
// BM=128, BN=128, BK=32. 3-stage cp.async pipeline. 8 warps (4 M x 2 N), warp tile 32x64.
#define LDS       40                    // smem stride in halves (80B) - conflict free
#define TILE_B    (128 * LDS * 2)       // 10240 bytes per [128][32] bf16 tile
#define OFF_AHI   0
#define OFF_ALO   (TILE_B)
#define OFF_BHI   (2 * TILE_B)
#define OFF_BLO   (3 * TILE_B)
#define STAGE_B   (4 * TILE_B)          // 40960
#define NSTAGE    3
#define SM_TOTAL  (NSTAGE * STAGE_B)    // 122880

__device__ __forceinline__ void load_tile(uint32_t sdst, const __nv_bfloat16* __restrict__ g,
                                          int row0, int K, int k0, int tid)
{
    const char* gb = (const char*)(g + (size_t)row0 * K + k0);
#pragma unroll
    for (int idx = tid; idx < 512; idx += 256) {
        const int r = idx >> 2;
        const int c = idx & 3;
        cp16(sdst + r * (LDS * 2) + c * 16, gb + (size_t)r * K * 2 + c * 16);
    }
}

template <int WRITE_HILO>
__global__ __launch_bounds__(256, 1)
void gemm_mma_x3(const __nv_bfloat16* __restrict__ Ahi, const __nv_bfloat16* __restrict__ Alo,
                 const __nv_bfloat16* __restrict__ Bhi, const __nv_bfloat16* __restrict__ Blo,
                 const float* __restrict__ bias,
                 __nv_bfloat16* __restrict__ Chi, __nv_bfloat16* __restrict__ Clo,
                 float* __restrict__ Cf,
                 int K, int N)
{
    extern __shared__ char smem[];
    const uint32_t sb = smem_u32(smem);
    const int tid  = threadIdx.x;
    const int wid  = tid >> 5;
    const int lane = tid & 31;
    const int wm   = wid & 3;        // 0..3 (M)
    const int wn   = wid >> 2;       // 0..1 (N)

    const int bm = blockIdx.y * 128;
    const int bn = blockIdx.x * 128;
    const int NK = K / 32;

    float acc[2][8][4];
#pragma unroll
    for (int mt = 0; mt < 2; mt++)
#pragma unroll
        for (int nb = 0; nb < 8; nb++)
#pragma unroll
            for (int q = 0; q < 4; q++) acc[mt][nb][q] = 0.0f;

    // prologue: prefetch stages 0, 1
#pragma unroll
    for (int s = 0; s < NSTAGE - 1; s++) {
        const uint32_t st = sb + s * STAGE_B;
        load_tile(st + OFF_AHI, Ahi, bm, K, s * 32, tid);
        load_tile(st + OFF_ALO, Alo, bm, K, s * 32, tid);
        load_tile(st + OFF_BHI, Bhi, bn, K, s * 32, tid);
        load_tile(st + OFF_BLO, Blo, bn, K, s * 32, tid);
        cp_commit();
    }

    // ldmatrix lane addressing (within-tile offsets, in bytes)
    const uint32_t a_lane_off = ((lane & 15) * LDS + (lane >> 4) * 8) * 2;
    const uint32_t b_lane_off = ((((lane >> 4) * 8) + (lane & 7)) * LDS + (((lane >> 3) & 1) * 8)) * 2;
    const uint32_t a_base_off = (wm * 32) * (LDS * 2);
    const uint32_t b_base_off = (wn * 64) * (LDS * 2);

    for (int c = 0; c < NK; c++) {
        cp_wait<NSTAGE - 2>();
        __syncthreads();

        // prefetch stage c + NSTAGE-1 into the slot just freed
        const int pf = c + NSTAGE - 1;
        if (pf < NK) {
            const uint32_t st = sb + (pf % NSTAGE) * STAGE_B;
            load_tile(st + OFF_AHI, Ahi, bm, K, pf * 32, tid);
            load_tile(st + OFF_ALO, Alo, bm, K, pf * 32, tid);
            load_tile(st + OFF_BHI, Bhi, bn, K, pf * 32, tid);
            load_tile(st + OFF_BLO, Blo, bn, K, pf * 32, tid);
        }
        cp_commit();

        const uint32_t st = sb + (c % NSTAGE) * STAGE_B;
        const uint32_t sAh = st + OFF_AHI + a_base_off + a_lane_off;
        const uint32_t sAl = st + OFF_ALO + a_base_off + a_lane_off;
        const uint32_t sBh = st + OFF_BHI + b_base_off + b_lane_off;
        const uint32_t sBl = st + OFF_BLO + b_base_off + b_lane_off;

#pragma unroll
        for (int kk = 0; kk < 2; kk++) {
            const uint32_t ko = kk * 16 * 2;
            uint32_t ah[2][4], al[2][4];
#pragma unroll
            for (int mt = 0; mt < 2; mt++) {
                ldm_x4(ah[mt][0], ah[mt][1], ah[mt][2], ah[mt][3], sAh + mt * 16 * (LDS * 2) + ko);
                ldm_x4(al[mt][0], al[mt][1], al[mt][2], al[mt][3], sAl + mt * 16 * (LDS * 2) + ko);
            }
            uint32_t bh[4][4], bl[4][4];   // pair p covers n-blocks 2p (r0,r1) and 2p+1 (r2,r3)
#pragma unroll
            for (int p = 0; p < 4; p++) {
                ldm_x4(bh[p][0], bh[p][1], bh[p][2], bh[p][3], sBh + p * 16 * (LDS * 2) + ko);
                ldm_x4(bl[p][0], bl[p][1], bl[p][2], bl[p][3], sBl + p * 16 * (LDS * 2) + ko);
            }
            // product 1: Ahi * Bhi
#pragma unroll
            for (int mt = 0; mt < 2; mt++)
#pragma unroll
                for (int nb = 0; nb < 8; nb++) {
                    const uint32_t* b = bh[nb >> 1];
                    const int o = (nb & 1) * 2;
                    mma16816(acc[mt][nb], ah[mt], b[o], b[o + 1]);
                }
            // product 2: Ahi * Blo
#pragma unroll
            for (int mt = 0; mt < 2; mt++)
#pragma unroll
                for (int nb = 0; nb < 8; nb++) {
                    const uint32_t* b = bl[nb >> 1];
                    const int o = (nb & 1) * 2;
                    mma16816(acc[mt][nb], ah[mt], b[o], b[o + 1]);
                }
            // product 3: Alo * Bhi
#pragma unroll
            for (int mt = 0; mt < 2; mt++)
#pragma unroll
                for (int nb = 0; nb < 8; nb++) {
                    const uint32_t* b = bh[nb >> 1];
                    const int o = (nb & 1) * 2;
                    mma16816(acc[mt][nb], al[mt], b[o], b[o + 1]);
                }
        }
        __syncthreads();
    }

    // ---------------- epilogue: bias + ReLU ----------------
#pragma unroll
    for (int mt = 0; mt < 2; mt++) {
        const int row0 = bm + wm * 32 + mt * 16 + (lane >> 2);
#pragma unroll
        for (int nb = 0; nb < 8; nb++) {
            const int col = bn + wn * 64 + nb * 8 + (lane & 3) * 2;
            const float bx = bias[col];
            const float by = bias[col + 1];
            float y0 = fmaxf(acc[mt][nb][0] + bx, 0.0f);
            float y1 = fmaxf(acc[mt][nb][1] + by, 0.0f);
            float y2 = fmaxf(acc[mt][nb][2] + bx, 0.0f);
            float y3 = fmaxf(acc[mt][nb][3] + by, 0.0f);
            if (WRITE_HILO) {
                __nv_bfloat16 h0 = __float2bfloat16(y0), h1 = __float2bfloat16(y1);
                __nv_bfloat16 h2 = __float2bfloat16(y2), h3 = __float2bfloat16(y3);
                __nv_bfloat16 l0 = __float2bfloat16(y0 - __bfloat162float(h0));
                __nv_bfloat16 l1 = __float2bfloat16(y1 - __bfloat162float(h1));
                __nv_bfloat16 l2 = __float2bfloat16(y2 - __bfloat162float(h2));
                __nv_bfloat16 l3 = __float2bfloat16(y3 - __bfloat162float(h3));
                *(__nv_bfloat162*)(Chi + (size_t)row0 * N + col)       = __nv_bfloat162(h0, h1);
                *(__nv_bfloat162*)(Chi + (size_t)(row0 + 8) * N + col) = __nv_bfloat162(h2, h3);
                *(__nv_bfloat162*)(Clo + (size_t)row0 * N + col)       = __nv_bfloat162(l0, l1);
                *(__nv_bfloat162*)(Clo + (size_t)(row0 + 8) * N + col) = __nv_bfloat162(l2, l3);
            } else {
                *(float2*)(Cf + (size_t)row0 * N + col)       = make_float2(y0, y1);
                *(float2*)(Cf + (size_t)(row0 + 8) * N + col) = make_float2(y2, y3);
            }
        }
    }
}

// ---------------- conversion kernels ----------------
__global__ __launch_bounds__(256)
void split_f32(const float* __restrict__ in, __nv_bfloat16* __restrict__ hi,
               __nv_bfloat16* __restrict__ lo, size_t n4)
{
    size_t i = (size_t)blockIdx.x * blockDim.x + threadIdx.x;
    if (i >= n4) return;
    float4 v = ((const float4*)in)[i];
    __nv_bfloat16 h0 = __float2bfloat16(v.x), h1 = __float2bfloat16(v.y);
    __nv_bfloat16 h2 = __float2bfloat16(v.z), h3 = __float2bfloat16(v.w);
    __nv_bfloat16 l0 = __float2bfloat16(v.x - __bfloat162float(h0));
    __nv_bfloat16 l1 = __float2bfloat16(v.y - __bfloat162float(h1));
    __nv_bfloat16 l2 = __float2bfloat16(v.z - __bfloat162float(h2));
    __nv_bfloat16 l3 = __float2bfloat16(v.w - __bfloat162float(h3));
    ((__nv_bfloat162*)hi)[i * 2 + 0] = __nv_bfloat162(h0, h1);
    ((__nv_bfloat162*)hi)[i * 2 + 1] = __nv_bfloat162(h2, h3);
    ((__nv_bfloat162*)lo)[i * 2 + 0] = __nv_bfloat162(l0, l1);
    ((__nv_bfloat162*)lo)[i * 2 + 1] = __nv_bfloat162(l2, l3);
}

// in: [K][N] fp32 row-major -> out hi/lo: [N][K] bf16 row-major
__global__ __launch_bounds__(256)
void transpose_split(const float* __restrict__ in, __nv_bfloat16* __restrict__ hi,
                     __nv_bfloat16* __restrict__ lo, int K, int N)
{
    __shared__ float t[32][33];
    const int k0 = blockIdx.y * 32;
    const int n0 = blockIdx.x * 32;
    const int tx = threadIdx.x;
    const int ty = threadIdx.y;
#pragma unroll
    for (int r = 0; r < 4; r++) {
        const int k = k0 + ty * 4 + r;
        t[ty * 4 + r][tx] = in[(size_t)k * N + n0 + tx];
    }
    __syncthreads();
#pragma unroll
    for (int r = 0; r < 4; r++) {
        const int n = n0 + ty * 4 + r;
        const float v = t[tx][ty * 4 + r];
        const __nv_bfloat16 h = __float2bfloat16(v);
        const __nv_bfloat16 l = __float2bfloat16(v - __bfloat162float(h));
        hi[(size_t)n * K + k0 + tx] = h;
        lo[(size_t)n * K + k0 + tx] = l;
    }
}

// ---------------- heads ----------------
__global__ __launch_bounds__(256)
void heads_kernel(const float* __restrict__ H,
                  const float* __restrict__ Wc, const float* __restrict__ bc,
                  const float* __restrict__ Wr, const float* __restrict__ br,
                  float* __restrict__ out, int M)
{
    const int warp = (blockIdx.x * blockDim.x + threadIdx.x) >> 5;
    const int lane = threadIdx.x & 31;
    if (warp >= M) return;

    const float* __restrict__ h = H + (size_t)warp * D_HID;
    float acc[16];
#pragma unroll
    for (int c = 0; c < 16; c++) acc[c] = 0.0f;

    for (int k = lane; k < D_HID; k += 32) {
        const float x = h[k];
        const float* wc = Wc + (size_t)k * 4;
#pragma unroll
        for (int c = 0; c < 4; c++) acc[c] = fmaf(x, wc[c], acc[c]);
        const float* wr = Wr + (size_t)k * 12;
#pragma unroll
        for (int c = 0; c < 12; c++) acc[4 + c] = fmaf(x, wr[c], acc[4 + c]);
    }
#pragma unroll
    for (int c = 0; c < 16; c++)
#pragma unroll
        for (int off = 16; off > 0; off >>= 1)
            acc[c] += __shfl_xor_sync(0xffffffffu, acc[c], off);

    if (lane < 4) {
        out[(size_t)warp * 4 + lane] = acc[lane] + bc[lane];
    } else if (lane < 16) {
        out[(size_t)M * 4 + (size_t)warp * 12 + (lane - 4)] = acc[lane] + br[lane - 4];
    }
}

// ---------------- host ----------------
extern "C" void kernel_launch(void* const* d_in, const int* in_sizes, int n_in,
                              void* d_out, int out_size)
{
    const float* X  = (const float*)d_in[0];
    const float* W1 = (const float*)d_in[1];
    const float* b1 = (const float*)d_in[2];
    const float* W2 = (const float*)d_in[3];
    const float* b2 = (const float*)d_in[4];
    const float* Wc = (const float*)d_in[5];
    const float* bc = (const float*)d_in[6];
    const float* Wr = (const float*)d_in[7];
    const float* br = (const float*)d_in[8];
    float* out = (float*)d_out;

    const int M = in_sizes[0] / D_IN;   // 16000

    __nv_bfloat16 *Xhi, *Xlo, *W1hi, *W1lo, *W2hi, *W2lo, *h1hi, *h1lo;
    float* h2;
    cudaGetSymbolAddress((void**)&Xhi, g_Xhi);
    cudaGetSymbolAddress((void**)&Xlo, g_Xlo);
    cudaGetSymbolAddress((void**)&W1hi, g_W1hi);
    cudaGetSymbolAddress((void**)&W1lo, g_W1lo);
    cudaGetSymbolAddress((void**)&W2hi, g_W2hi);
    cudaGetSymbolAddress((void**)&W2lo, g_W2lo);
    cudaGetSymbolAddress((void**)&h1hi, g_h1hi);
    cudaGetSymbolAddress((void**)&h1lo, g_h1lo);
    cudaGetSymbolAddress((void**)&h2, g_h2);

    // conversions
    {
        const size_t n4 = (size_t)M * D_IN / 4;
        split_f32<<<(unsigned)((n4 + 255) / 256), 256>>>(X, Xhi, Xlo, n4);
        dim3 tb(32, 8);
        transpose_split<<<dim3(D_HID / 32, D_IN / 32), tb>>>(W1, W1hi, W1lo, D_IN, D_HID);
        transpose_split<<<dim3(D_HID / 32, D_HID / 32), tb>>>(W2, W2hi, W2lo, D_HID, D_HID);
    }

    cudaFuncSetAttribute(gemm_mma_x3<1>, cudaFuncAttributeMaxDynamicSharedMemorySize, SM_TOTAL);
    cudaFuncSetAttribute(gemm_mma_x3<0>, cudaFuncAttributeMaxDynamicSharedMemorySize, SM_TOTAL);

    dim3 grid(D_HID / 128, M / 128);   // (8, 125)
    gemm_mma_x3<1><<<grid, 256, SM_TOTAL>>>(Xhi, Xlo, W1hi, W1lo, b1, h1hi, h1lo, nullptr, D_IN, D_HID);
    gemm_mma_x3<0><<<grid, 256, SM_TOTAL>>>(h1hi, h1lo, W2hi, W2lo, b2, nullptr, nullptr, h2, D_HID, D_HID);

    const int threads = 256;
    const int blocks = (M * 32 + threads - 1) / threads;
    heads_kernel<<<blocks, threads>>>(h2, Wc, bc, Wr, br, out, M);
}

// round 4
// speedup vs baseline: 2.3314x; 1.0817x over previous
#include <cuda_runtime.h>
#include <cuda_bf16.h>
#include <cstdint>
#include <cstddef>

#define D_IN  12544
#define D_HID 1024
#define MAXN  16000

// ---------------- device scratch (allocation-free rule) ----------------
__device__ __align__(1024) __nv_bfloat16 g_Xhi[(size_t)MAXN * D_IN];
__device__ __align__(1024) __nv_bfloat16 g_Xlo[(size_t)MAXN * D_IN];
__device__ __align__(1024) __nv_bfloat16 g_W1hi[(size_t)D_HID * D_IN];  // [N][K]
__device__ __align__(1024) __nv_bfloat16 g_W1lo[(size_t)D_HID * D_IN];
__device__ __align__(1024) __nv_bfloat16 g_W2hi[(size_t)D_HID * D_HID];
__device__ __align__(1024) __nv_bfloat16 g_W2lo[(size_t)D_HID * D_HID];
__device__ __align__(1024) __nv_bfloat16 g_h1hi[(size_t)MAXN * D_HID];
__device__ __align__(1024) __nv_bfloat16 g_h1lo[(size_t)MAXN * D_HID];
__device__ float g_h2[(size_t)MAXN * D_HID];

// ---------------- asm helpers ----------------
__device__ __forceinline__ uint32_t smem_u32(const void* p) {
    uint32_t a;
    asm("{ .reg .u64 t; cvta.to.shared.u64 t, %1; cvt.u32.u64 %0, t; }" : "=r"(a) : "l"(p));
    return a;
}
__device__ __forceinline__ void cp16(uint32_t dst, const void* src) {
    asm volatile("cp.async.cg.shared.global [%0], [%1], 16;" :: "r"(dst), "l"(src));
}
__device__ __forceinline__ void cp_commit() {
    asm volatile("cp.async.commit_group;" ::: "memory");
}
template <int N>
__device__ __forceinline__ void cp_wait() {
    asm volatile("cp.async.wait_group %0;" :: "n"(N) : "memory");
}
__device__ __forceinline__ void ldm_x4(uint32_t& r0, uint32_t& r1, uint32_t& r2, uint32_t& r3, uint32_t addr) {
    asm volatile("ldmatrix.sync.aligned.m8n8.x4.shared.b16 {%0,%1,%2,%3}, [%4];"
                 : "=r"(r0), "=r"(r1), "=r"(r2), "=r"(r3) : "r"(addr));
}
__device__ __forceinline__ void mma16816(float* c, const uint32_t* a, uint32_t b0, uint32_t b1) {
    asm volatile(
        "mma.sync.aligned.m16n8k16.row.col.f32.bf16.bf16.f32 "
        "{%0,%1,%2,%3}, {%4,%5,%6,%7}, {%8,%9}, {%0,%1,%2,%3};"
        : "+f"(c[0]), "+f"(c[1]), "+f"(c[2]), "+f"(c[3])
        : "r"(a[0]), "r"(a[1]), "r"(a[2]), "r"(a[3]), "r"(b0), "r"(b1));
}

// ---------------- GEMM: C[M,N] = act(A[M,K] @ B[N,K]^T + bias), bf16 hi/lo x3 ----------------
// BM=128, BN=128, BK=32. 3-stage cp.async pipeline. 16 warps (4 M x 4 N), warp tile 32x32.
#define LDS       40                    // smem stride in halves (80B) - conflict free
#define TILE_B    (128 * LDS * 2)       // 10240 bytes per [128][32] bf16 tile
#define OFF_AHI   0
#define OFF_ALO   (TILE_B)
#define OFF_BHI   (2 * TILE_B)
#define OFF_BLO   (3 * TILE_B)
#define STAGE_B   (4 * TILE_B)          // 40960
#define NSTAGE    3
#define SM_TOTAL  (NSTAGE * STAGE_B)    // 122880

__device__ __forceinline__ void load_tile(uint32_t sdst, const __nv_bfloat16* __restrict__ g,
                                          int row0, int K, int k0, int tid)
{
    // 512 threads, 512 x 16B chunks: one chunk per thread
    const char* gb = (const char*)(g + (size_t)row0 * K + k0);
    const int r = tid >> 2;
    const int c = tid & 3;
    cp16(sdst + r * (LDS * 2) + c * 16, gb + (size_t)r * K * 2 + c * 16);
}

template <int WRITE_HILO>
__global__ __launch_bounds__(512, 1)
void gemm_mma_x3(const __nv_bfloat16* __restrict__ Ahi, const __nv_bfloat16* __restrict__ Alo,
                 const __nv_bfloat16* __restrict__ Bhi, const __nv_bfloat16* __restrict__ Blo,
                 const float* __restrict__ bias,
                 __nv_bfloat16* __restrict__ Chi, __nv_bfloat16* __restrict__ Clo,
                 float* __restrict__ Cf,
                 int K, int N)
{
    extern __shared__ char smem[];
    const uint32_t sb = smem_u32(smem);
    const int tid  = threadIdx.x;
    const int wid  = tid >> 5;
    const int lane = tid & 31;
    const int wm   = wid & 3;        // 0..3 (M)
    const int wn   = wid >> 2;       // 0..3 (N)

    const int bm = blockIdx.y * 128;
    const int bn = blockIdx.x * 128;
    const int NK = K / 32;

    float acc[2][4][4];
#pragma unroll
    for (int mt = 0; mt < 2; mt++)
#pragma unroll
        for (int nb = 0; nb < 4; nb++)
#pragma unroll
            for (int q = 0; q < 4; q++) acc[mt][nb][q] = 0.0f;

    // prologue: prefetch stages 0, 1
#pragma unroll
    for (int s = 0; s < NSTAGE - 1; s++) {
        const uint32_t st = sb + s * STAGE_B;
        load_tile(st + OFF_AHI, Ahi, bm, K, s * 32, tid);
        load_tile(st + OFF_ALO, Alo, bm, K, s * 32, tid);
        load_tile(st + OFF_BHI, Bhi, bn, K, s * 32, tid);
        load_tile(st + OFF_BLO, Blo, bn, K, s * 32, tid);
        cp_commit();
    }

    // ldmatrix lane addressing (within-tile offsets, in bytes)
    const uint32_t a_lane_off = ((lane & 15) * LDS + (lane >> 4) * 8) * 2;
    const uint32_t b_lane_off = ((((lane >> 4) * 8) + (lane & 7)) * LDS + (((lane >> 3) & 1) * 8)) * 2;
    const uint32_t a_base_off = (wm * 32) * (LDS * 2);
    const uint32_t b_base_off = (wn * 32) * (LDS * 2);

    for (int c = 0; c < NK; c++) {
        cp_wait<NSTAGE - 2>();
        __syncthreads();

        // prefetch stage c + NSTAGE-1 into the slot just freed
        const int pf = c + NSTAGE - 1;
        if (pf < NK) {
            const uint32_t st = sb + (pf % NSTAGE) * STAGE_B;
            load_tile(st + OFF_AHI, Ahi, bm, K, pf * 32, tid);
            load_tile(st + OFF_ALO, Alo, bm, K, pf * 32, tid);
            load_tile(st + OFF_BHI, Bhi, bn, K, pf * 32, tid);
            load_tile(st + OFF_BLO, Blo, bn, K, pf * 32, tid);
        }
        cp_commit();

        const uint32_t st = sb + (c % NSTAGE) * STAGE_B;
        const uint32_t sAh = st + OFF_AHI + a_base_off + a_lane_off;
        const uint32_t sAl = st + OFF_ALO + a_base_off + a_lane_off;
        const uint32_t sBh = st + OFF_BHI + b_base_off + b_lane_off;
        const uint32_t sBl = st + OFF_BLO + b_base_off + b_lane_off;

#pragma unroll
        for (int kk = 0; kk < 2; kk++) {
            const uint32_t ko = kk * 16 * 2;
            uint32_t ah[2][4], al[2][4];
#pragma unroll
            for (int mt = 0; mt < 2; mt++) {
                ldm_x4(ah[mt][0], ah[mt][1], ah[mt][2], ah[mt][3], sAh + mt * 16 * (LDS * 2) + ko);
                ldm_x4(al[mt][0], al[mt][1], al[mt][2], al[mt][3], sAl + mt * 16 * (LDS * 2) + ko);
            }
            uint32_t bh[2][4], bl[2][4];   // pair p covers n-blocks 2p (r0,r1) and 2p+1 (r2,r3)
#pragma unroll
            for (int p = 0; p < 2; p++) {
                ldm_x4(bh[p][0], bh[p][1], bh[p][2], bh[p][3], sBh + p * 16 * (LDS * 2) + ko);
                ldm_x4(bl[p][0], bl[p][1], bl[p][2], bl[p][3], sBl + p * 16 * (LDS * 2) + ko);
            }
            // product 1: Ahi * Bhi
#pragma unroll
            for (int mt = 0; mt < 2; mt++)
#pragma unroll
                for (int nb = 0; nb < 4; nb++) {
                    const uint32_t* b = bh[nb >> 1];
                    const int o = (nb & 1) * 2;
                    mma16816(acc[mt][nb], ah[mt], b[o], b[o + 1]);
                }
            // product 2: Ahi * Blo
#pragma unroll
            for (int mt = 0; mt < 2; mt++)
#pragma unroll
                for (int nb = 0; nb < 4; nb++) {
                    const uint32_t* b = bl[nb >> 1];
                    const int o = (nb & 1) * 2;
                    mma16816(acc[mt][nb], ah[mt], b[o], b[o + 1]);
                }
            // product 3: Alo * Bhi
#pragma unroll
            for (int mt = 0; mt < 2; mt++)
#pragma unroll
                for (int nb = 0; nb < 4; nb++) {
                    const uint32_t* b = bh[nb >> 1];
                    const int o = (nb & 1) * 2;
                    mma16816(acc[mt][nb], al[mt], b[o], b[o + 1]);
                }
        }
        __syncthreads();
    }

    // ---------------- epilogue: bias + ReLU ----------------
#pragma unroll
    for (int mt = 0; mt < 2; mt++) {
        const int row0 = bm + wm * 32 + mt * 16 + (lane >> 2);
#pragma unroll
        for (int nb = 0; nb < 4; nb++) {
            const int col = bn + wn * 32 + nb * 8 + (lane & 3) * 2;
            const float bx = bias[col];
            const float by = bias[col + 1];
            float y0 = fmaxf(acc[mt][nb][0] + bx, 0.0f);
            float y1 = fmaxf(acc[mt][nb][1] + by, 0.0f);
            float y2 = fmaxf(acc[mt][nb][2] + bx, 0.0f);
            float y3 = fmaxf(acc[mt][nb][3] + by, 0.0f);
            if (WRITE_HILO) {
                __nv_bfloat16 h0 = __float2bfloat16(y0), h1 = __float2bfloat16(y1);
                __nv_bfloat16 h2 = __float2bfloat16(y2), h3 = __float2bfloat16(y3);
                __nv_bfloat16 l0 = __float2bfloat16(y0 - __bfloat162float(h0));
                __nv_bfloat16 l1 = __float2bfloat16(y1 - __bfloat162float(h1));
                __nv_bfloat16 l2 = __float2bfloat16(y2 - __bfloat162float(h2));
                __nv_bfloat16 l3 = __float2bfloat16(y3 - __bfloat162float(h3));
                *(__nv_bfloat162*)(Chi + (size_t)row0 * N + col)       = __nv_bfloat162(h0, h1);
                *(__nv_bfloat162*)(Chi + (size_t)(row0 + 8) * N + col) = __nv_bfloat162(h2, h3);
                *(__nv_bfloat162*)(Clo + (size_t)row0 * N + col)       = __nv_bfloat162(l0, l1);
                *(__nv_bfloat162*)(Clo + (size_t)(row0 + 8) * N + col) = __nv_bfloat162(l2, l3);
            } else {
                *(float2*)(Cf + (size_t)row0 * N + col)       = make_float2(y0, y1);
                *(float2*)(Cf + (size_t)(row0 + 8) * N + col) = make_float2(y2, y3);
            }
        }
    }
}

// ---------------- conversion kernels ----------------
__global__ __launch_bounds__(256)
void split_f32(const float* __restrict__ in, __nv_bfloat16* __restrict__ hi,
               __nv_bfloat16* __restrict__ lo, size_t n4)
{
    size_t i = (size_t)blockIdx.x * blockDim.x + threadIdx.x;
    if (i >= n4) return;
    float4 v = ((const float4*)in)[i];
    __nv_bfloat16 h0 = __float2bfloat16(v.x), h1 = __float2bfloat16(v.y);
    __nv_bfloat16 h2 = __float2bfloat16(v.z), h3 = __float2bfloat16(v.w);
    __nv_bfloat16 l0 = __float2bfloat16(v.x - __bfloat162float(h0));
    __nv_bfloat16 l1 = __float2bfloat16(v.y - __bfloat162float(h1));
    __nv_bfloat16 l2 = __float2bfloat16(v.z - __bfloat162float(h2));
    __nv_bfloat16 l3 = __float2bfloat16(v.w - __bfloat162float(h3));
    ((__nv_bfloat162*)hi)[i * 2 + 0] = __nv_bfloat162(h0, h1);
    ((__nv_bfloat162*)hi)[i * 2 + 1] = __nv_bfloat162(h2, h3);
    ((__nv_bfloat162*)lo)[i * 2 + 0] = __nv_bfloat162(l0, l1);
    ((__nv_bfloat162*)lo)[i * 2 + 1] = __nv_bfloat162(l2, l3);
}

// in: [K][N] fp32 row-major -> out hi/lo: [N][K] bf16 row-major
__global__ __launch_bounds__(256)
void transpose_split(const float* __restrict__ in, __nv_bfloat16* __restrict__ hi,
                     __nv_bfloat16* __restrict__ lo, int K, int N)
{
    __shared__ float t[32][33];
    const int k0 = blockIdx.y * 32;
    const int n0 = blockIdx.x * 32;
    const int tx = threadIdx.x;
    const int ty = threadIdx.y;
#pragma unroll
    for (int r = 0; r < 4; r++) {
        const int k = k0 + ty * 4 + r;
        t[ty * 4 + r][tx] = in[(size_t)k * N + n0 + tx];
    }
    __syncthreads();
#pragma unroll
    for (int r = 0; r < 4; r++) {
        const int n = n0 + ty * 4 + r;
        const float v = t[tx][ty * 4 + r];
        const __nv_bfloat16 h = __float2bfloat16(v);
        const __nv_bfloat16 l = __float2bfloat16(v - __bfloat162float(h));
        hi[(size_t)n * K + k0 + tx] = h;
        lo[(size_t)n * K + k0 + tx] = l;
    }
}

// ---------------- heads ----------------
__global__ __launch_bounds__(256)
void heads_kernel(const float* __restrict__ H,
                  const float* __restrict__ Wc, const float* __restrict__ bc,
                  const float* __restrict__ Wr, const float* __restrict__ br,
                  float* __restrict__ out, int M)
{
    const int warp = (blockIdx.x * blockDim.x + threadIdx.x) >> 5;
    const int lane = threadIdx.x & 31;
    if (warp >= M) return;

    const float* __restrict__ h = H + (size_t)warp * D_HID;
    float acc[16];
#pragma unroll
    for (int c = 0; c < 16; c++) acc[c] = 0.0f;

    for (int k = lane; k < D_HID; k += 32) {
        const float x = h[k];
        const float* wc = Wc + (size_t)k * 4;
#pragma unroll
        for (int c = 0; c < 4; c++) acc[c] = fmaf(x, wc[c], acc[c]);
        const float* wr = Wr + (size_t)k * 12;
#pragma unroll
        for (int c = 0; c < 12; c++) acc[4 + c] = fmaf(x, wr[c], acc[4 + c]);
    }
#pragma unroll
    for (int c = 0; c < 16; c++)
#pragma unroll
        for (int off = 16; off > 0; off >>= 1)
            acc[c] += __shfl_xor_sync(0xffffffffu, acc[c], off);

    if (lane < 4) {
        out[(size_t)warp * 4 + lane] = acc[lane] + bc[lane];
    } else if (lane < 16) {
        out[(size_t)M * 4 + (size_t)warp * 12 + (lane - 4)] = acc[lane] + br[lane - 4];
    }
}

// ---------------- host ----------------
extern "C" void kernel_launch(void* const* d_in, const int* in_sizes, int n_in,
                              void* d_out, int out_size)
{
    const float* X  = (const float*)d_in[0];
    const float* W1 = (const float*)d_in[1];
    const float* b1 = (const float*)d_in[2];
    const float* W2 = (const float*)d_in[3];
    const float* b2 = (const float*)d_in[4];
    const float* Wc = (const float*)d_in[5];
    const float* bc = (const float*)d_in[6];
    const float* Wr = (const float*)d_in[7];
    const float* br = (const float*)d_in[8];
    float* out = (float*)d_out;

    const int M = in_sizes[0] / D_IN;   // 16000

    __nv_bfloat16 *Xhi, *Xlo, *W1hi, *W1lo, *W2hi, *W2lo, *h1hi, *h1lo;
    float* h2;
    cudaGetSymbolAddress((void**)&Xhi, g_Xhi);
    cudaGetSymbolAddress((void**)&Xlo, g_Xlo);
    cudaGetSymbolAddress((void**)&W1hi, g_W1hi);
    cudaGetSymbolAddress((void**)&W1lo, g_W1lo);
    cudaGetSymbolAddress((void**)&W2hi, g_W2hi);
    cudaGetSymbolAddress((void**)&W2lo, g_W2lo);
    cudaGetSymbolAddress((void**)&h1hi, g_h1hi);
    cudaGetSymbolAddress((void**)&h1lo, g_h1lo);
    cudaGetSymbolAddress((void**)&h2, g_h2);

    // conversions
    {
        const size_t n4 = (size_t)M * D_IN / 4;
        split_f32<<<(unsigned)((n4 + 255) / 256), 256>>>(X, Xhi, Xlo, n4);
        dim3 tb(32, 8);
        transpose_split<<<dim3(D_HID / 32, D_IN / 32), tb>>>(W1, W1hi, W1lo, D_IN, D_HID);
        transpose_split<<<dim3(D_HID / 32, D_HID / 32), tb>>>(W2, W2hi, W2lo, D_HID, D_HID);
    }

    cudaFuncSetAttribute(gemm_mma_x3<1>, cudaFuncAttributeMaxDynamicSharedMemorySize, SM_TOTAL);
    cudaFuncSetAttribute(gemm_mma_x3<0>, cudaFuncAttributeMaxDynamicSharedMemorySize, SM_TOTAL);

    dim3 grid(D_HID / 128, M / 128);   // (8, 125)
    gemm_mma_x3<1><<<grid, 512, SM_TOTAL>>>(Xhi, Xlo, W1hi, W1lo, b1, h1hi, h1lo, nullptr, D_IN, D_HID);
    gemm_mma_x3<0><<<grid, 512, SM_TOTAL>>>(h1hi, h1lo, W2hi, W2lo, b2, nullptr, nullptr, h2, D_HID, D_HID);

    const int threads = 256;
    const int blocks = (M * 32 + threads - 1) / threads;
    heads_kernel<<<blocks, threads>>>(h2, Wc, bc, Wr, br, out, M);
}